// round 7
// baseline (speedup 1.0000x reference)
#include <cuda_runtime.h>
#include <math.h>

#define NP 200000
#define NA 200000
#define NT (NP + NA)          // combined node space: P = [0,NP), A = [NP,NT)
#define NE 2000000
#define E2 (2 * NE)
#define H  64
#define DP 128
#define DA 64
#define OUTD 32

// ---------------------------------------------------------------------------
// Device scratch (no cudaMalloc allowed)
// ---------------------------------------------------------------------------
__device__ float g_feat[(size_t)NT * H];
__device__ float g_x[(size_t)NT * H];
__device__ float g_x1[NT];
__device__ float g_h1[NT];
__device__ float g_w2[NT];
__device__ int g_rptr[NT + 1];
__device__ int g_ctgt[E2];
__device__ int g_counts[NT + 1];
__device__ int g_cursor[NT + 1];
__device__ int g_bsums[512];

__device__ __forceinline__ float leaky02(float v) {
    return v > 0.0f ? v : 0.2f * v;
}

// ---------------------------------------------------------------------------
// CSR build kernels (combined edge space)
// ---------------------------------------------------------------------------
__global__ void zero_int_kernel(int* p, int n) {
    int i = blockIdx.x * blockDim.x + threadIdx.x;
    if (i < n) p[i] = 0;
}

__global__ void hist_kernel(const int* __restrict__ ei_pa, const int* __restrict__ ei_ap,
                            int* __restrict__ counts) {
    int i = blockIdx.x * blockDim.x + threadIdx.x;
    if (i < E2) {
        int s = (i < NE) ? ei_pa[i] : (NP + ei_ap[i - NE]);
        atomicAdd(&counts[s], 1);
    }
}

__global__ void block_sums_kernel(const int* __restrict__ c, int n, int* __restrict__ bs) {
    __shared__ int sd[1024];
    int i = blockIdx.x * 1024 + threadIdx.x;
    sd[threadIdx.x] = (i < n) ? c[i] : 0;
    __syncthreads();
    for (int o = 512; o; o >>= 1) {
        if (threadIdx.x < o) sd[threadIdx.x] += sd[threadIdx.x + o];
        __syncthreads();
    }
    if (threadIdx.x == 0) bs[blockIdx.x] = sd[0];
}

__global__ void scan_bs_kernel(int* bs, int nb) {   // nb <= 512
    __shared__ int s[512];
    int tid = threadIdx.x;
    int v = tid < nb ? bs[tid] : 0;
    s[tid] = v;
    __syncthreads();
    for (int o = 1; o < 512; o <<= 1) {
        int u = (tid >= o) ? s[tid - o] : 0;
        __syncthreads();
        s[tid] += u;
        __syncthreads();
    }
    if (tid < nb) bs[tid] = s[tid] - v;
}

__global__ void scan_final_kernel(const int* __restrict__ c, int n,
                                  const int* __restrict__ bs, int* __restrict__ rptr) {
    __shared__ int sd[1024];
    int i = blockIdx.x * 1024 + threadIdx.x;
    int v = (i < n) ? c[i] : 0;
    sd[threadIdx.x] = v;
    __syncthreads();
    for (int o = 1; o < 1024; o <<= 1) {
        int u = (threadIdx.x >= o) ? sd[threadIdx.x - o] : 0;
        __syncthreads();
        sd[threadIdx.x] += u;
        __syncthreads();
    }
    int excl = sd[threadIdx.x] - v + bs[blockIdx.x];
    if (i < n) rptr[i] = excl;
    if (i == n - 1) rptr[n] = excl + v;
}

__global__ void copy_int_kernel(const int* __restrict__ a, int* __restrict__ b, int n) {
    int i = blockIdx.x * blockDim.x + threadIdx.x;
    if (i < n) b[i] = a[i];
}

__global__ void scatter_kernel(const int* __restrict__ ei_pa, const int* __restrict__ ei_ap,
                               int* __restrict__ cursor, int* __restrict__ ctgt) {
    int i = blockIdx.x * blockDim.x + threadIdx.x;
    if (i < E2) {
        int s, t;
        if (i < NE) { s = ei_pa[i];            t = NP + ei_pa[NE + i]; }
        else        { s = NP + ei_ap[i - NE];  t = ei_ap[NE + (i - NE)]; }
        int pos = atomicAdd(&cursor[s], 1);
        ctgt[pos] = t;
    }
}

// ---------------------------------------------------------------------------
// Double-buffered register-blocked SGEMM: Y[N, BN] = act(X[N, K] @ W[K, BN] + b)
// BM=128, BK=16, 128 threads, thread tile TM=8 x TN=BN/8.
// Prefetch tile t+1 into registers while computing tile t; one barrier/tile.
// PREP: fused attention-prep epilogue.
// ---------------------------------------------------------------------------
template<int K, int BN, bool RELU, bool PREP>
__global__ void __launch_bounds__(128)
gemm_kernel(const float* __restrict__ X, const float* __restrict__ W,
            const float* __restrict__ bias, float* __restrict__ Y, int N,
            const float* __restrict__ a1P, const float* __restrict__ a2P,
            const float* __restrict__ aoP,
            const float* __restrict__ a1A, const float* __restrict__ a2A,
            const float* __restrict__ aoA,
            float* __restrict__ x1o, float* __restrict__ h1o, float* __restrict__ w2o)
{
    constexpr int BM = 128;
    constexpr int BK = 16;
    constexpr int TM = 8;
    constexpr int TN = BN / 8;              // 8 for BN=64, 4 for BN=32
    constexpr int NITER = K / BK;
    constexpr int WPT = (BK * BN / 4) / 128; // W float4s per thread: 2 (BN=64) / 1 (BN=32)

    __shared__ float sX[2][BK][BM];
    __shared__ float sW[2][BK * BN];

    const int tid = threadIdx.x;
    const int tr  = tid >> 3;
    const int tc  = tid & 7;
    const int r0  = blockIdx.x * BM;

    float acc[TM][TN];
    #pragma unroll
    for (int j = 0; j < TN; j++) {
        float bv = bias[tc * TN + j];
        #pragma unroll
        for (int r = 0; r < TM; r++) acc[r][j] = bv;
    }

    int gr = r0 + tid;
    if (gr >= N) gr = N - 1;
    const float* xrow = X + (size_t)gr * K;

    float4 px[4], pw[WPT];

    // Prefetch tile 0
    px[0] = *(const float4*)(xrow + 0);
    px[1] = *(const float4*)(xrow + 4);
    px[2] = *(const float4*)(xrow + 8);
    px[3] = *(const float4*)(xrow + 12);
    {
        const float4* wsrc = (const float4*)(W);
        #pragma unroll
        for (int i = 0; i < WPT; i++) pw[i] = wsrc[tid + i * 128];
    }
    // Store tile 0 into buffer 0
    #pragma unroll
    for (int v = 0; v < 4; v++) {
        sX[0][v * 4 + 0][tid] = px[v].x;
        sX[0][v * 4 + 1][tid] = px[v].y;
        sX[0][v * 4 + 2][tid] = px[v].z;
        sX[0][v * 4 + 3][tid] = px[v].w;
    }
    {
        float4* wdst = (float4*)&sW[0][0];
        #pragma unroll
        for (int i = 0; i < WPT; i++) wdst[tid + i * 128] = pw[i];
    }
    __syncthreads();

    #pragma unroll
    for (int t = 0; t < NITER; t++) {
        const int cur = t & 1;

        // Prefetch tile t+1 into registers (overlaps with compute below)
        if (t + 1 < NITER) {
            const int k0 = (t + 1) * BK;
            px[0] = *(const float4*)(xrow + k0);
            px[1] = *(const float4*)(xrow + k0 + 4);
            px[2] = *(const float4*)(xrow + k0 + 8);
            px[3] = *(const float4*)(xrow + k0 + 12);
            const float4* wsrc = (const float4*)(W + (size_t)k0 * BN);
            #pragma unroll
            for (int i = 0; i < WPT; i++) pw[i] = wsrc[tid + i * 128];
        }

        // Compute on buffer cur
        #pragma unroll
        for (int kk = 0; kk < BK; kk++) {
            float xr[TM];
            *(float4*)(xr)     = *(const float4*)(&sX[cur][kk][tr * TM]);
            *(float4*)(xr + 4) = *(const float4*)(&sX[cur][kk][tr * TM + 4]);
            float wr[TN];
            #pragma unroll
            for (int j = 0; j < TN; j += 4)
                *(float4*)(wr + j) = *(const float4*)(&sW[cur][kk * BN + tc * TN + j]);
            #pragma unroll
            for (int r = 0; r < TM; r++)
                #pragma unroll
                for (int j = 0; j < TN; j++)
                    acc[r][j] += xr[r] * wr[j];
        }

        // Store prefetched tile into the other buffer
        if (t + 1 < NITER) {
            const int nxt = 1 - cur;
            #pragma unroll
            for (int v = 0; v < 4; v++) {
                sX[nxt][v * 4 + 0][tid] = px[v].x;
                sX[nxt][v * 4 + 1][tid] = px[v].y;
                sX[nxt][v * 4 + 2][tid] = px[v].z;
                sX[nxt][v * 4 + 3][tid] = px[v].w;
            }
            float4* wdst = (float4*)&sW[nxt][0];
            #pragma unroll
            for (int i = 0; i < WPT; i++) wdst[tid + i * 128] = pw[i];
            __syncthreads();
        }
    }

    // Epilogue: activation + store
    #pragma unroll
    for (int r = 0; r < TM; r++) {
        int q = r0 + tr * TM + r;
        if (q < N) {
            if (RELU) {
                #pragma unroll
                for (int j = 0; j < TN; j++) acc[r][j] = fmaxf(acc[r][j], 0.0f);
            }
            #pragma unroll
            for (int j = 0; j < TN; j += 4)
                *(float4*)(Y + (size_t)q * BN + tc * TN + j) = *(float4*)(&acc[r][j]);
        }
    }

    if (PREP) {
        const int rowbase = r0 + tr * TM;
        const bool isP = (rowbase < NP);
        const float* v1 = isP ? a1P : a1A;
        const float* v2 = isP ? a2P : a2A;
        const float* v3 = isP ? aoP : aoA;
        float s1[TN], s2[TN], s3[TN];
        #pragma unroll
        for (int j = 0; j < TN; j += 4) {
            *(float4*)(s1 + j) = *(const float4*)(v1 + tc * TN + j);
            *(float4*)(s2 + j) = *(const float4*)(v2 + tc * TN + j);
            *(float4*)(s3 + j) = *(const float4*)(v3 + tc * TN + j);
        }
        #pragma unroll
        for (int r = 0; r < TM; r++) {
            float p1 = 0.f, p2 = 0.f, p3 = 0.f;
            #pragma unroll
            for (int j = 0; j < TN; j++) {
                p1 += acc[r][j] * s1[j];
                p2 += acc[r][j] * s2[j];
                p3 += acc[r][j] * s3[j];
            }
            #pragma unroll
            for (int o = 4; o; o >>= 1) {
                p1 += __shfl_xor_sync(0xFFFFFFFFu, p1, o);
                p2 += __shfl_xor_sync(0xFFFFFFFFu, p2, o);
                p3 += __shfl_xor_sync(0xFFFFFFFFu, p3, o);
            }
            int q = rowbase + r;
            if (tc == 0 && q < N) {
                x1o[q] = p1;
                h1o[q] = p3;
                w2o[q] = __expf(leaky02(p1 + p2));
            }
        }
    }
}

// ---------------------------------------------------------------------------
// CSR aggregation + finalize: one warp per source node (combined space).
// ---------------------------------------------------------------------------
__global__ void __launch_bounds__(256)
csr_agg_kernel(const int* __restrict__ rptr, const int* __restrict__ ctgt,
               const float* __restrict__ x, const float* __restrict__ x1,
               const float* __restrict__ w2arr, const float* __restrict__ h1,
               float* __restrict__ outfeat, int N)
{
    int s = (blockIdx.x * blockDim.x + threadIdx.x) >> 5;
    int lane = threadIdx.x & 31;
    if (s >= N) return;

    int beg = rptr[s];
    int end = rptr[s + 1];
    float x1s = x1[s];
    float w2  = w2arr[s];

    float2 xv = *(const float2*)(x + (size_t)s * H + lane * 2);
    float2 accA; accA.x = w2 * xv.x; accA.y = w2 * xv.y;
    float2 accB; accB.x = 0.f; accB.y = 0.f;
    float divA = w2, divB = 0.f;

    for (int base = beg; base < end; base += 32) {
        int myIdx = base + lane;
        int t = 0; float h1t = 0.0f;
        if (myIdx < end) {
            t = ctgt[myIdx];
            h1t = h1[t];
        }
        int cnt = min(32, end - base);
        int i = 0;
        for (; i + 1 < cnt; i += 2) {
            int   t0 = __shfl_sync(0xFFFFFFFFu, t, i);
            float g0 = __shfl_sync(0xFFFFFFFFu, h1t, i);
            int   t1 = __shfl_sync(0xFFFFFFFFu, t, i + 1);
            float g1 = __shfl_sync(0xFFFFFFFFu, h1t, i + 1);
            float w0 = __expf(leaky02(x1s + g0));
            float w1 = __expf(leaky02(x1s + g1));
            float2 hv0 = *(const float2*)(x + (size_t)t0 * H + lane * 2);
            float2 hv1 = *(const float2*)(x + (size_t)t1 * H + lane * 2);
            accA.x += w0 * hv0.x; accA.y += w0 * hv0.y; divA += w0;
            accB.x += w1 * hv1.x; accB.y += w1 * hv1.y; divB += w1;
        }
        if (i < cnt) {
            int   t0 = __shfl_sync(0xFFFFFFFFu, t, i);
            float g0 = __shfl_sync(0xFFFFFFFFu, h1t, i);
            float w0 = __expf(leaky02(x1s + g0));
            float2 hv0 = *(const float2*)(x + (size_t)t0 * H + lane * 2);
            accA.x += w0 * hv0.x; accA.y += w0 * hv0.y; divA += w0;
        }
    }

    float divv = divA + divB;
    float inv = 1.0f / divv;
    float vx = (accA.x + accB.x) * inv;
    float vy = (accA.y + accB.y) * inv;
    vx = vx > 0.0f ? vx : (__expf(vx) - 1.0f);
    vy = vy > 0.0f ? vy : (__expf(vy) - 1.0f);
    float2 o; o.x = vx; o.y = vy;
    *(float2*)(outfeat + (size_t)s * H + lane * 2) = o;
}

// ---------------------------------------------------------------------------
// Launch
// ---------------------------------------------------------------------------
extern "C" void kernel_launch(void* const* d_in, const int* in_sizes, int n_in,
                              void* d_out, int out_size)
{
    const float* x_P     = (const float*)d_in[0];
    const float* x_A     = (const float*)d_in[1];
    const int*   ei_pa   = (const int*)d_in[2];
    const int*   ei_ap   = (const int*)d_in[3];
    const float* fc1_P_w = (const float*)d_in[4];
    const float* fc1_P_b = (const float*)d_in[5];
    const float* fc1_A_w = (const float*)d_in[6];
    const float* fc1_A_b = (const float*)d_in[7];
    const float* fcs_w   = (const float*)d_in[8];
    const float* fcs_b   = (const float*)d_in[9];
    const float* a1_pa   = (const float*)d_in[10];
    const float* a2_pa   = (const float*)d_in[11];
    const float* a1_ap   = (const float*)d_in[12];
    const float* a2_ap   = (const float*)d_in[13];
    const float* fc2_w   = (const float*)d_in[14];
    const float* fc2_b   = (const float*)d_in[15];
    float* out = (float*)d_out;

    float *feat, *x, *x1, *h1, *w2;
    int *rptr, *ctgt, *counts, *cursor, *bsums;
    cudaGetSymbolAddress((void**)&feat,   g_feat);
    cudaGetSymbolAddress((void**)&x,      g_x);
    cudaGetSymbolAddress((void**)&x1,     g_x1);
    cudaGetSymbolAddress((void**)&h1,     g_h1);
    cudaGetSymbolAddress((void**)&w2,     g_w2);
    cudaGetSymbolAddress((void**)&rptr,   g_rptr);
    cudaGetSymbolAddress((void**)&ctgt,   g_ctgt);
    cudaGetSymbolAddress((void**)&counts, g_counts);
    cudaGetSymbolAddress((void**)&cursor, g_cursor);
    cudaGetSymbolAddress((void**)&bsums,  g_bsums);

    const int NB = (NT + 1023) / 1024;
    const int gemmP_blocks  = (NP + 127) / 128;
    const int gemmT_blocks  = (NT + 127) / 128;
    const int agg_blocks    = (NT + 7) / 8;

    // --- CSR build interleaved with independent GEMMs ---
    zero_int_kernel<<<(NT + 255) / 256, 256>>>(counts, NT);
    hist_kernel<<<(E2 + 255) / 256, 256>>>(ei_pa, ei_ap, counts);
    block_sums_kernel<<<NB, 1024>>>(counts, NT, bsums);

    gemm_kernel<DP, H, true, false><<<gemmP_blocks, 128>>>(
        x_P, fc1_P_w, fc1_P_b, feat, NP,
        nullptr,nullptr,nullptr,nullptr,nullptr,nullptr,nullptr,nullptr,nullptr);
    gemm_kernel<DA, H, true, false><<<gemmP_blocks, 128>>>(
        x_A, fc1_A_w, fc1_A_b, feat + (size_t)NP * H, NA,
        nullptr,nullptr,nullptr,nullptr,nullptr,nullptr,nullptr,nullptr,nullptr);

    gemm_kernel<H, H, false, true><<<gemmT_blocks, 128>>>(
        feat, fcs_w, fcs_b, x, NT,
        a1_pa, a2_pa, a2_ap,
        a1_ap, a2_ap, a2_pa,
        x1, h1, w2);

    scan_bs_kernel<<<1, 512>>>(bsums, NB);
    scan_final_kernel<<<NB, 1024>>>(counts, NT, bsums, rptr);
    copy_int_kernel<<<(NT + 255) / 256, 256>>>(rptr, cursor, NT);
    scatter_kernel<<<(E2 + 255) / 256, 256>>>(ei_pa, ei_ap, cursor, ctgt);

    csr_agg_kernel<<<agg_blocks, 256>>>(rptr, ctgt, x, x1, w2, h1, feat, NT);

    gemm_kernel<H, H, false, true><<<gemmT_blocks, 128>>>(
        feat, fcs_w + (size_t)H * H, fcs_b + H, x, NT,
        a1_pa + H, a2_pa + H, a2_ap + H,
        a1_ap + H, a2_ap + H, a2_pa + H,
        x1, h1, w2);
    csr_agg_kernel<<<agg_blocks, 256>>>(rptr, ctgt, x, x1, w2, h1, feat, NT);

    gemm_kernel<H, OUTD, false, false><<<gemmP_blocks, 128>>>(
        feat, fc2_w, fc2_b, out, NP,
        nullptr,nullptr,nullptr,nullptr,nullptr,nullptr,nullptr,nullptr,nullptr);
}